// round 2
// baseline (speedup 1.0000x reference)
#include <cuda_runtime.h>
#include <cuda_fp16.h>
#include <cstdint>

// ============================================================================
// BitLinear: out[16384, 2048] = X[16384, 2048] @ T^T * scale + bias
// T = ternary(W) exact in fp16, X in fp16, fp32 accumulate via mma.sync (HMMA).
// (tcgen05 unavailable: harness PTX targets sm_103 without the 'a' feature.)
// ============================================================================

#define M_TOTAL 16384
#define N_TOTAL 2048
#define K_TOTAL 2048

#define BM 128
#define BN 128
#define BK 64
#define STAGES 3
#define KITERS (K_TOTAL / BK)          // 32

#define A_TILE_BYTES (BM * BK * 2)     // 16384
#define B_TILE_BYTES (BN * BK * 2)     // 16384
#define STAGE_BYTES  (A_TILE_BYTES + B_TILE_BYTES)   // 32768
#define SMEM_BYTES   (STAGES * STAGE_BYTES)          // 98304

// Scratch (device globals: allocation-free per harness rules)
__device__ __half g_Xh[(size_t)M_TOTAL * K_TOTAL];   // 64 MB
__device__ __half g_Wq[(size_t)N_TOTAL * K_TOTAL];   // 8 MB
__device__ float  g_scale[N_TOTAL];

// ---------------------------------------------------------------------------
// helpers
// ---------------------------------------------------------------------------
__device__ __forceinline__ uint32_t smem_u32(const void* p) {
    uint32_t a;
    asm("{ .reg .u64 t; cvta.to.shared.u64 t, %1; cvt.u32.u64 %0, t; }" : "=r"(a) : "l"(p));
    return a;
}
__device__ __forceinline__ void cp_async16(uint32_t s, const void* g) {
    asm volatile("cp.async.cg.shared.global [%0], [%1], 16;" :: "r"(s), "l"(g));
}
__device__ __forceinline__ void cp_commit() { asm volatile("cp.async.commit_group;"); }
template <int N> __device__ __forceinline__ void cp_wait() {
    asm volatile("cp.async.wait_group %0;" :: "n"(N));
}
__device__ __forceinline__ uint32_t swz(uint32_t off) { return off ^ ((off >> 3) & 0x70); }

__device__ __forceinline__ void ldsm_x4(uint32_t& r0, uint32_t& r1, uint32_t& r2,
                                        uint32_t& r3, uint32_t addr) {
    asm volatile("ldmatrix.sync.aligned.m8n8.x4.shared.b16 {%0,%1,%2,%3}, [%4];"
                 : "=r"(r0), "=r"(r1), "=r"(r2), "=r"(r3) : "r"(addr));
}
__device__ __forceinline__ void mma16816(float& c0, float& c1, float& c2, float& c3,
                                         uint32_t a0, uint32_t a1, uint32_t a2, uint32_t a3,
                                         uint32_t b0, uint32_t b1) {
    asm volatile(
        "mma.sync.aligned.m16n8k16.row.col.f32.f16.f16.f32 "
        "{%0,%1,%2,%3}, {%4,%5,%6,%7}, {%8,%9}, {%0,%1,%2,%3};"
        : "+f"(c0), "+f"(c1), "+f"(c2), "+f"(c3)
        : "r"(a0), "r"(a1), "r"(a2), "r"(a3), "r"(b0), "r"(b1));
}

// ---------------------------------------------------------------------------
// Prep 1: ternarize W -> fp16 T (exact) + fp32 scale
// ---------------------------------------------------------------------------
__global__ void ternarize_kernel(const float* __restrict__ w) {
    __shared__ float red[8];
    int row = blockIdx.x;
    const float* wr = w + (size_t)row * K_TOTAL;
    float m = 0.f;
    for (int i = threadIdx.x; i < K_TOTAL; i += 256)
        m = fmaxf(m, fabsf(wr[i]));
    #pragma unroll
    for (int o = 16; o; o >>= 1) m = fmaxf(m, __shfl_xor_sync(0xffffffffu, m, o));
    if ((threadIdx.x & 31) == 0) red[threadIdx.x >> 5] = m;
    __syncthreads();
    if (threadIdx.x < 8) {
        float v = red[threadIdx.x];
        #pragma unroll
        for (int o = 4; o; o >>= 1) v = fmaxf(v, __shfl_xor_sync(0xffu, v, o));
        if (threadIdx.x == 0) red[0] = v;
    }
    __syncthreads();
    float s = fmaxf(red[0], 1e-6f);
    if (threadIdx.x == 0) g_scale[row] = s;
    for (int i = threadIdx.x; i < K_TOTAL; i += 256) {
        float v = __fdiv_rn(wr[i], s);   // IEEE div: match reference at +/-0.5 boundary
        float t = (v > 0.5f) ? 1.f : ((v < -0.5f) ? -1.f : 0.f);
        g_Wq[(size_t)row * K_TOTAL + i] = __float2half_rn(t);
    }
}

// ---------------------------------------------------------------------------
// Prep 2: X fp32 -> fp16
// ---------------------------------------------------------------------------
__global__ void cvt_x_kernel(const float4* __restrict__ x, int n4) {
    int i = blockIdx.x * blockDim.x + threadIdx.x;
    if (i < n4) {
        float4 v = x[i];
        __half2* dst = (__half2*)g_Xh;
        dst[2 * (size_t)i + 0] = __floats2half2_rn(v.x, v.y);
        dst[2 * (size_t)i + 1] = __floats2half2_rn(v.z, v.w);
    }
}

// ---------------------------------------------------------------------------
// GEMM: mma.sync m16n8k16 + 3-stage cp.async pipeline
// 256 threads (8 warps, 4x2), warp tile 32x64, CTA tile 128x128
// ---------------------------------------------------------------------------
extern __shared__ char dyn_smem[];

__device__ __forceinline__ void load_stage(uint32_t sb, int tid, int slot, int kt,
                                           const char* Ab, const char* Bb) {
    uint32_t a_s = sb + slot * STAGE_BYTES;
    uint32_t b_s = a_s + A_TILE_BYTES;
    int r0 = tid >> 3;           // 0..31
    int ch = tid & 7;            // 0..7 (16B chunks)
    size_t gcol = (size_t)kt * 128 + ch * 16;   // byte offset along K
    #pragma unroll
    for (int j = 0; j < 4; j++) {
        int r = r0 + j * 32;
        uint32_t so = swz((uint32_t)(r * 128 + ch * 16));
        cp_async16(a_s + so, Ab + (size_t)r * (K_TOTAL * 2) + gcol);
        cp_async16(b_s + so, Bb + (size_t)r * (K_TOTAL * 2) + gcol);
    }
}

__global__ void __launch_bounds__(256, 2) gemm_kernel(float* __restrict__ out,
                                                      const float* __restrict__ bias) {
    uint32_t sb = smem_u32(dyn_smem);
    int tid = threadIdx.x, wid = tid >> 5, lane = tid & 31;
    int warp_m = wid & 3;        // 4 warps over M (32 rows each)
    int warp_n = wid >> 2;       // 2 warps over N (64 cols each)

    int nt = blockIdx.x & 15;    // 16 N-tiles: consecutive CTAs share A tile in L2
    int mt = blockIdx.x >> 4;

    const char* Ab = (const char*)(g_Xh + (size_t)mt * BM * K_TOTAL);
    const char* Bb = (const char*)(g_Wq + (size_t)nt * BN * K_TOTAL);

    float c[2][8][4];
    #pragma unroll
    for (int mi = 0; mi < 2; mi++)
        #pragma unroll
        for (int nf = 0; nf < 8; nf++)
            #pragma unroll
            for (int q = 0; q < 4; q++) c[mi][nf][q] = 0.f;

    // ldmatrix lane-address components (byte offsets within tile, pre-swizzle)
    // A x4: lanes 0-15 -> rows m0..15 (k 0-7), lanes 16-31 -> same rows (k 8-15)
    int a_row = warp_m * 32 + (lane & 15);
    int a_kh  = (lane >> 4) * 8;
    // B x4 covering nf pair (2p, 2p+1): group g = lane>>3
    //   n_row = p*16 + (g>>1)*8 + (lane&7), k_half = (g&1)*8
    int b_g   = lane >> 3;
    int b_row = warp_n * 64 + ((b_g >> 1) << 3) + (lane & 7);
    int b_kh  = (b_g & 1) * 8;

    // prologue
    #pragma unroll
    for (int s = 0; s < STAGES - 1; s++) {
        load_stage(sb, tid, s, s, Ab, Bb);
        cp_commit();
    }

    for (int it = 0; it < KITERS; it++) {
        cp_wait<STAGES - 2>();
        __syncthreads();

        int nxt = it + STAGES - 1;
        if (nxt < KITERS)
            load_stage(sb, tid, nxt % STAGES, nxt, Ab, Bb);
        cp_commit();

        uint32_t a_s = sb + (it % STAGES) * STAGE_BYTES;
        uint32_t b_s = a_s + A_TILE_BYTES;

        #pragma unroll
        for (int kk = 0; kk < 4; kk++) {
            uint32_t a[2][4];
            #pragma unroll
            for (int mi = 0; mi < 2; mi++) {
                uint32_t off = (uint32_t)((a_row + mi * 16) * 128 + (kk * 16 + a_kh) * 2);
                ldsm_x4(a[mi][0], a[mi][1], a[mi][2], a[mi][3], a_s + swz(off));
            }
            uint32_t b[8][2];
            #pragma unroll
            for (int p = 0; p < 4; p++) {
                uint32_t off = (uint32_t)((b_row + p * 16) * 128 + (kk * 16 + b_kh) * 2);
                uint32_t r0, r1, r2, r3;
                ldsm_x4(r0, r1, r2, r3, b_s + swz(off));
                b[2 * p + 0][0] = r0; b[2 * p + 0][1] = r1;
                b[2 * p + 1][0] = r2; b[2 * p + 1][1] = r3;
            }
            #pragma unroll
            for (int mi = 0; mi < 2; mi++)
                #pragma unroll
                for (int nf = 0; nf < 8; nf++)
                    mma16816(c[mi][nf][0], c[mi][nf][1], c[mi][nf][2], c[mi][nf][3],
                             a[mi][0], a[mi][1], a[mi][2], a[mi][3],
                             b[nf][0], b[nf][1]);
        }
    }

    // epilogue: scale * acc + bias, float2 stores
    int gid = lane >> 2, tig = lane & 3;
    int col_base = nt * BN + warp_n * 64 + tig * 2;
    int row_base = mt * BM + warp_m * 32 + gid;
    #pragma unroll
    for (int nf = 0; nf < 8; nf++) {
        int col = col_base + nf * 8;
        float s0 = g_scale[col], s1 = g_scale[col + 1];
        float b0 = bias[col],    b1 = bias[col + 1];
        #pragma unroll
        for (int mi = 0; mi < 2; mi++) {
            int r0 = row_base + mi * 16;
            float2 v0 = make_float2(c[mi][nf][0] * s0 + b0, c[mi][nf][1] * s1 + b1);
            float2 v1 = make_float2(c[mi][nf][2] * s0 + b0, c[mi][nf][3] * s1 + b1);
            *(float2*)(out + (size_t)r0 * N_TOTAL + col)       = v0;
            *(float2*)(out + (size_t)(r0 + 8) * N_TOTAL + col) = v1;
        }
    }
}

// ---------------------------------------------------------------------------
// launch
// ---------------------------------------------------------------------------
extern "C" void kernel_launch(void* const* d_in, const int* in_sizes, int n_in,
                              void* d_out, int out_size) {
    const float* x = nullptr;
    const float* w = nullptr;
    const float* bias = nullptr;
    for (int i = 0; i < n_in; i++) {
        if (in_sizes[i] == M_TOTAL * K_TOTAL)      x    = (const float*)d_in[i];
        else if (in_sizes[i] == N_TOTAL * K_TOTAL) w    = (const float*)d_in[i];
        else if (in_sizes[i] == N_TOTAL)           bias = (const float*)d_in[i];
    }
    float* out = (float*)d_out;

    ternarize_kernel<<<N_TOTAL, 256>>>(w);

    int n4 = (M_TOTAL * K_TOTAL) / 4;
    cvt_x_kernel<<<(n4 + 255) / 256, 256>>>((const float4*)x, n4);

    cudaFuncSetAttribute(gemm_kernel, cudaFuncAttributeMaxDynamicSharedMemorySize, SMEM_BYTES);
    gemm_kernel<<<(M_TOTAL / BM) * (N_TOTAL / BN), 256, SMEM_BYTES>>>(out, bias);
}